// round 14
// baseline (speedup 1.0000x reference)
#include <cuda_runtime.h>
#include <cuda_bf16.h>
#include <math.h>
#include <stdint.h>

// ============================================================================
// GraphCut loss, R14: 3 launches. k_fsum folded into kernel tails via tickets.
//  - k_prep: convert+seeds+hist+zero counters.
//  - k_phase1: verification scan; LAST CTA (ticket) computes the output
//    directly when g_flagcnt==0 (all neg-sums provably exact fp32 zeros).
//  - k_exact: exact fallback; when flag!=0 its LAST CTA reduces g_pm -> out
//    (stream order guarantees it overwrites any phase1 fast-path write).
// Exactness: all off-diag s_ij <= seed-109 => every reference exp underflows
// to exact fp32 zero (exp(x)==0 for x<=-105); violations -> exact fallback.
// ============================================================================

#define MD 8192
#define KD 128
#define NCLS 20
#define NBLK 64
#define NQ 2048
#define NTILES (NQ / 128)
#define THRESH 105.0f
#define SLACK 109.0f

#define P1_CTAS 444
#define P1_PER 9                 // 444*9 + 164 = 4160
#define P1_EXTRA 164
#define EX_CTAS 256

__device__ __align__(16) __nv_bfloat16 g_featB[(size_t)MD * KD];  // 2MB, *sqrt(5)
__device__ float  g_thr[MD];      // seed_i - SLACK
__device__ int    g_flagcnt;
__device__ float2 g_pm[4 * MD];   // fallback partials
__device__ int    g_hist[NCLS];
__device__ int    g_p1done, g_exdone;

// ---------------------------------------------------------------- helpers
__device__ __forceinline__ uint32_t smem_u32(const void* p) {
    uint32_t a;
    asm("{ .reg .u64 t; cvta.to.shared.u64 t, %1; cvt.u32.u64 %0, t; }" : "=r"(a) : "l"(p));
    return a;
}
#define CP_ASYNC16(dst, src) \
    asm volatile("cp.async.cg.shared.global [%0], [%1], 16;" :: "r"(dst), "l"(src) : "memory")
#define CP_COMMIT() asm volatile("cp.async.commit_group;" ::: "memory")
#define CP_WAIT0()  asm volatile("cp.async.wait_group 0;" ::: "memory")
#define LDSM_X4(r0, r1, r2, r3, a) \
    asm volatile("ldmatrix.sync.aligned.m8n8.x4.shared.b16 {%0,%1,%2,%3}, [%4];" \
                 : "=r"(r0), "=r"(r1), "=r"(r2), "=r"(r3) : "r"(a))
#define MMA16816(c, a0, a1, a2, a3, b0, b1) \
    asm volatile("mma.sync.aligned.m16n8k16.row.col.f32.bf16.bf16.f32 " \
                 "{%0,%1,%2,%3},{%4,%5,%6,%7},{%8,%9},{%0,%1,%2,%3};" \
                 : "+f"((c)[0]), "+f"((c)[1]), "+f"((c)[2]), "+f"((c)[3]) \
                 : "r"(a0), "r"(a1), "r"(a2), "r"(a3), "r"(b0), "r"(b1))

// --------------------------- prep: convert + seeds + hist + zeroing
__global__ void k_prep(const float* __restrict__ feat,
                       const int* __restrict__ labels) {
    __shared__ int sh[NCLS];
    const float SC = 2.23606797749979f;   // sqrt(1/0.2)
    int tid = threadIdx.x;
    int bid = blockIdx.x;
    int i = (bid * 256 + tid) * 8;

    if (bid == 0) {
        if (tid < NCLS) g_hist[tid] = 0;
        if (tid == 0) { g_flagcnt = 0; g_p1done = 0; g_exdone = 0; }
    }

    float4 f0 = *(const float4*)&feat[i];
    float4 f1 = *(const float4*)&feat[i + 4];
    union { __nv_bfloat16 h[8]; uint4 u; } U;
    U.h[0] = __float2bfloat16(f0.x * SC); U.h[1] = __float2bfloat16(f0.y * SC);
    U.h[2] = __float2bfloat16(f0.z * SC); U.h[3] = __float2bfloat16(f0.w * SC);
    U.h[4] = __float2bfloat16(f1.x * SC); U.h[5] = __float2bfloat16(f1.y * SC);
    U.h[6] = __float2bfloat16(f1.z * SC); U.h[7] = __float2bfloat16(f1.w * SC);
    *(uint4*)&g_featB[i] = U.u;
    float s = 0.0f;
#pragma unroll
    for (int e = 0; e < 8; e++) {
        float v = __bfloat162float(U.h[e]);
        s = fmaf(v, v, s);
    }
#pragma unroll
    for (int off = 1; off <= 8; off <<= 1)
        s += __shfl_xor_sync(0xffffffffu, s, off);
    if ((tid & 15) == 0)
        g_thr[bid * 16 + (tid >> 4)] = s - SLACK;

    // CTAs 1..8 build the label histogram (avoid CTA0's zeroing race).
    if (bid >= 1 && bid <= 8) {
        if (tid < NCLS) sh[tid] = 0;
        __syncthreads();
        int4 L = ((const int4*)labels)[(bid - 1) * 256 + tid];
        int l0 = L.x, l1 = L.y, l2 = L.z, l3 = L.w;
        l0 = l0 < 0 ? 0 : (l0 >= NCLS ? NCLS - 1 : l0);
        l1 = l1 < 0 ? 0 : (l1 >= NCLS ? NCLS - 1 : l1);
        l2 = l2 < 0 ? 0 : (l2 >= NCLS ? NCLS - 1 : l2);
        l3 = l3 < 0 ? 0 : (l3 >= NCLS ? NCLS - 1 : l3);
        atomicAdd(&sh[l0], 1); atomicAdd(&sh[l1], 1);
        atomicAdd(&sh[l2], 1); atomicAdd(&sh[l3], 1);
        __syncthreads();
        if (tid < NCLS) atomicAdd(&g_hist[tid], sh[tid]);
    }
}

// ---------------------------------------------------------------- tile fills
__device__ __forceinline__ void fillA256(char* A_s, int row0, int tid) {
#pragma unroll
    for (int v = 0; v < 8; v++) {
        int idx = tid + v * 256;
        int row = idx >> 4, c16 = idx & 15;
        uint4 val = *(const uint4*)&g_featB[(size_t)(row0 + row) * KD + c16 * 8];
        *(uint4*)(A_s + row * 256 + ((c16 ^ (row & 7)) << 4)) = val;
    }
}
__device__ __forceinline__ void fillB64_async(uint32_t bu, int row0, int tid) {
#pragma unroll
    for (int v = 0; v < 4; v++) {
        int idx = tid + v * 256;
        int row = idx >> 4, c16 = idx & 15;
        CP_ASYNC16(bu + row * 256 + ((c16 ^ (row & 7)) << 4),
                   &g_featB[(size_t)(row0 + row) * KD + c16 * 8]);
    }
}
__device__ __forceinline__ void fillA512(char* A_s, int row0, int tid) {
#pragma unroll
    for (int v = 0; v < 4; v++) {
        int idx = tid + v * 512;
        int row = idx >> 4, c16 = idx & 15;
        uint4 val = *(const uint4*)&g_featB[(size_t)(row0 + row) * KD + c16 * 8];
        *(uint4*)(A_s + row * 256 + ((c16 ^ (row & 7)) << 4)) = val;
    }
}
__device__ __forceinline__ void fillB128_async(uint32_t bu, int row0, int tid) {
#pragma unroll
    for (int v = 0; v < 4; v++) {
        int idx = tid + v * 512;
        int row = idx >> 4, c16 = idx & 15;
        CP_ASYNC16(bu + row * 256 + ((c16 ^ (row & 7)) << 4),
                   &g_featB[(size_t)(row0 + row) * KD + c16 * 8]);
    }
}

// ---------------------------------------------------------------- phase 1
__global__ void __launch_bounds__(256, 3)
k_phase1(const int* __restrict__ labels, const float* __restrict__ ious,
         float* __restrict__ out) {
    extern __shared__ char dsm[];
    char*  A_s   = dsm;                       // 32KB
    char*  B_s   = dsm + 32768;               // 2 x 16KB
    float* thrC  = (float*)(dsm + 65536);     // 2 x 64 floats
    float* sThrR = (float*)(dsm + 66048);     // 128 floats
    uint32_t A_u = smem_u32(A_s);
    uint32_t B_u = smem_u32(B_s);
    uint32_t thrC_u = smem_u32(thrC);

    int tid = threadIdx.x, lane = tid & 31, wid = tid >> 5;
    int wm = wid >> 1, wn = wid & 1;          // 4 x 2 warp grid
    int c = blockIdx.x;
    int base = c * P1_PER + (c < P1_EXTRA ? c : P1_EXTRA);
    int cnt  = P1_PER + (c < P1_EXTRA ? 1 : 0);

    int t0 = base >> 1;
    int h  = base & 1;
    int I = 0, tt = t0;
    while (tt >= NBLK - I) { tt -= NBLK - I; I++; }
    int J = I + tt;

    fillA256(A_s, I * 128, tid);
    if (tid < 128) sThrR[tid] = g_thr[I * 128 + tid];
    fillB64_async(B_u, J * 128 + h * 64, tid);
    if (tid < 16) CP_ASYNC16(thrC_u + tid * 16, &g_thr[J * 128 + h * 64 + tid * 4]);
    CP_COMMIT();

    int q  = lane >> 3;
    int kh = q >> 1;
    uint32_t aAddr[2]; int aRx[2];
#pragma unroll
    for (int mt = 0; mt < 2; mt++) {
        int row = wm * 32 + mt * 16 + (lane & 7) + ((q & 1) << 3);
        aAddr[mt] = A_u + row * 256;
        aRx[mt]   = row & 7;
    }
    uint32_t bOff[2]; int bRx[2];
#pragma unroll
    for (int bt = 0; bt < 2; bt++) {
        int row = wn * 32 + bt * 16 + (lane & 7) + ((q & 1) << 3);
        bOff[bt] = row * 256;
        bRx[bt]  = row & 7;
    }

    CP_WAIT0();
    __syncthreads();

    for (int it = 0; it < cnt; it++) {
        int In = I, Jn = J, hn = h ^ 1;
        if (hn == 0) {
            Jn = J + 1;
            if (Jn == NBLK) { In = I + 1; Jn = In; }
        }

        if (it + 1 < cnt) {
            uint32_t bu = B_u + ((it + 1) & 1) * 16384;
            fillB64_async(bu, Jn * 128 + hn * 64, tid);
            if (tid < 16)
                CP_ASYNC16(thrC_u + ((it + 1) & 1) * 256 + tid * 16,
                           &g_thr[Jn * 128 + hn * 64 + tid * 4]);
            CP_COMMIT();
        }

        uint32_t bu = B_u + (it & 1) * 16384;
        float acc[2][4][4];
#pragma unroll
        for (int a = 0; a < 2; a++)
#pragma unroll
            for (int b = 0; b < 4; b++)
#pragma unroll
                for (int cc = 0; cc < 4; cc++) acc[a][b][cc] = 0.0f;

#pragma unroll
        for (int ks = 0; ks < 8; ks++) {
            uint32_t b0[4], b1[4], a0[4], a1[4];
            LDSM_X4(b0[0], b0[1], b0[2], b0[3], bu + bOff[0] + (((ks * 2 + kh) ^ bRx[0]) << 4));
            LDSM_X4(b1[0], b1[1], b1[2], b1[3], bu + bOff[1] + (((ks * 2 + kh) ^ bRx[1]) << 4));
            LDSM_X4(a0[0], a0[1], a0[2], a0[3], aAddr[0] + (((ks * 2 + kh) ^ aRx[0]) << 4));
            LDSM_X4(a1[0], a1[1], a1[2], a1[3], aAddr[1] + (((ks * 2 + kh) ^ aRx[1]) << 4));
            MMA16816(acc[0][0], a0[0], a0[1], a0[2], a0[3], b0[0], b0[2]);
            MMA16816(acc[0][1], a0[0], a0[1], a0[2], a0[3], b0[1], b0[3]);
            MMA16816(acc[0][2], a0[0], a0[1], a0[2], a0[3], b1[0], b1[2]);
            MMA16816(acc[0][3], a0[0], a0[1], a0[2], a0[3], b1[1], b1[3]);
            MMA16816(acc[1][0], a1[0], a1[1], a1[2], a1[3], b0[0], b0[2]);
            MMA16816(acc[1][1], a1[0], a1[1], a1[2], a1[3], b0[1], b0[3]);
            MMA16816(acc[1][2], a1[0], a1[1], a1[2], a1[3], b1[0], b1[2]);
            MMA16816(acc[1][3], a1[0], a1[1], a1[2], a1[3], b1[1], b1[3]);
        }

        {
            int diag = (I == J);
            int cbase = h * 64;
            const float* tC = thrC + (it & 1) * 64;
            bool f = false;
#pragma unroll
            for (int mt = 0; mt < 2; mt++)
#pragma unroll
                for (int hh = 0; hh < 2; hh++) {
                    int rl = wm * 32 + mt * 16 + hh * 8 + (lane >> 2);
                    float tr = sThrR[rl];
#pragma unroll
                    for (int nt = 0; nt < 4; nt++)
#pragma unroll
                        for (int e = 0; e < 2; e++) {
                            int cl = wn * 32 + nt * 8 + (lane & 3) * 2 + e;
                            float v = acc[mt][nt][hh * 2 + e];
                            bool ex = diag && (rl == cbase + cl);
                            f |= (!ex) && ((v > tr) || (v > tC[cl]));
                        }
                }
            if (__any_sync(0xffffffffu, f) && lane == 0) atomicAdd(&g_flagcnt, 1);
        }

        CP_WAIT0();
        __syncthreads();

        if (it + 1 < cnt && In != I) {
            fillA256(A_s, In * 128, tid);
            if (tid < 128) sThrR[tid] = g_thr[In * 128 + tid];
            __syncthreads();
        }
        I = In; J = Jn; h = hn;
    }

    // -------- tail: last CTA computes output directly when flag==0 --------
    __shared__ int s_last;
    __threadfence();
    __syncthreads();
    if (tid == 0) s_last = (atomicAdd(&g_p1done, 1) == P1_CTAS - 1);
    __syncthreads();
    if (s_last) {
        int flg = atomicAdd(&g_flagcnt, 0);   // coherent read after all tickets
        if (flg == 0) {
            __shared__ float s_pc[NCLS];
            __shared__ float ss[8], sc2[8];
            if (tid < NCLS) s_pc[tid] = (float)(g_hist[tid] - 1);
            __syncthreads();
            float sum = 0.0f, cnt2 = 0.0f;
#pragma unroll
            for (int v = tid; v < MD / 4; v += 256) {
                float4 io = ((const float4*)ious)[v];
                int4 L = ((const int4*)labels)[v];
                float iv[4] = {io.x, io.y, io.z, io.w};
                int lv[4] = {L.x, L.y, L.z, L.w};
#pragma unroll
                for (int e = 0; e < 4; e++) {
                    int l = lv[e];
                    l = l < 0 ? 0 : (l >= NCLS ? NCLS - 1 : l);
                    if (iv[e] >= 0.5f) {
                        sum += 0.0f / s_pc[l];   // exact: ns==0; 0/0 -> nan
                        cnt2 += 1.0f;
                    }
                }
            }
#pragma unroll
            for (int off = 16; off > 0; off >>= 1) {
                sum  += __shfl_xor_sync(0xffffffffu, sum, off);
                cnt2 += __shfl_xor_sync(0xffffffffu, cnt2, off);
            }
            if ((tid & 31) == 0) { ss[tid >> 5] = sum; sc2[tid >> 5] = cnt2; }
            __syncthreads();
            if (tid == 0) {
                float S = 0.0f, C = 0.0f;
#pragma unroll
                for (int w = 0; w < 8; w++) { S += ss[w]; C += sc2[w]; }
                out[0] = S / C;
            }
        }
    }
}

// ---------------------------------------------------------------- exact fallback
__global__ void __launch_bounds__(512, 2)
k_exact(const int* __restrict__ labels, const float* __restrict__ ious,
        float* __restrict__ out) {
    if (g_flagcnt == 0) return;               // phase1 tail already wrote out
    extern __shared__ char dsm[];
    __shared__ float2 s_red[128][4];
    __shared__ float  s_seed[128];

    char* A_s  = dsm;
    char* B_s  = dsm + 32768;
    unsigned char* sLbl = (unsigned char*)(dsm + 98304);
    uint32_t A_u = smem_u32(A_s);
    uint32_t B_u = smem_u32(B_s);

    int tid  = threadIdx.x;
    int lane = tid & 31;
    int wid  = tid >> 5;
    int wm   = wid >> 2;
    int wn   = wid & 3;
    int r    = blockIdx.x >> 2;
    int qd   = blockIdx.x & 3;
    int i0   = r * 128;
    int j0   = qd * NQ;

    fillA512(A_s, i0, tid);
    fillB128_async(B_u, j0, tid);
    CP_COMMIT();
    {
        int4 L = ((const int4*)(labels + j0))[tid];
        ((uint32_t*)sLbl)[tid] = (uint32_t)(L.x & 255) | ((uint32_t)(L.y & 255) << 8)
                               | ((uint32_t)(L.z & 255) << 16) | ((uint32_t)(L.w & 255) << 24);
    }
    {
        int sr = tid >> 2, sq = tid & 3;
        const uint4* rp = (const uint4*)&g_featB[(size_t)(i0 + sr) * KD + sq * 32];
        float sacc = 0.0f;
#pragma unroll
        for (int g = 0; g < 4; g++) {
            uint4 u = rp[g];
            uint32_t w[4] = {u.x, u.y, u.z, u.w};
#pragma unroll
            for (int e = 0; e < 4; e++) {
                float lo = __uint_as_float(w[e] << 16);
                float hi = __uint_as_float(w[e] & 0xffff0000u);
                sacc = fmaf(lo, lo, sacc);
                sacc = fmaf(hi, hi, sacc);
            }
        }
        sacc += __shfl_xor_sync(0xffffffffu, sacc, 1);
        sacc += __shfl_xor_sync(0xffffffffu, sacc, 2);
        if (sq == 0) s_seed[sr] = sacc;
    }

    int myLbl[4];
#pragma unroll
    for (int mt = 0; mt < 2; mt++)
#pragma unroll
        for (int hh = 0; hh < 2; hh++)
            myLbl[mt * 2 + hh] = labels[i0 + wm * 32 + mt * 16 + hh * 8 + (lane >> 2)];

    int q  = lane >> 3;
    int kh = q >> 1;
    uint32_t aAddr[2]; int aRx[2];
#pragma unroll
    for (int mt = 0; mt < 2; mt++) {
        int row = wm * 32 + mt * 16 + (lane & 7) + ((q & 1) << 3);
        aAddr[mt] = A_u + row * 256;
        aRx[mt]   = row & 7;
    }
    uint32_t bOff[2]; int bRx[2];
#pragma unroll
    for (int bt = 0; bt < 2; bt++) {
        int row = wn * 32 + bt * 16 + (lane & 7) + ((q & 1) << 3);
        bOff[bt] = row * 256;
        bRx[bt]  = row & 7;
    }

    CP_WAIT0();
    __syncthreads();

    float mrow[4], prow[4];
#pragma unroll
    for (int mt = 0; mt < 2; mt++)
#pragma unroll
        for (int hh = 0; hh < 2; hh++) {
            mrow[mt * 2 + hh] = s_seed[wm * 32 + mt * 16 + hh * 8 + (lane >> 2)];
            prow[mt * 2 + hh] = 0.0f;
        }

    for (int t = 0; t < NTILES; t++) {
        if (t + 1 < NTILES) {
            fillB128_async(B_u + ((t + 1) & 1) * 32768, j0 + (t + 1) * 128, tid);
            CP_COMMIT();
        }

        uint32_t bu = B_u + (t & 1) * 32768;
        float acc[2][4][4];
#pragma unroll
        for (int a = 0; a < 2; a++)
#pragma unroll
            for (int b = 0; b < 4; b++)
#pragma unroll
                for (int cc = 0; cc < 4; cc++) acc[a][b][cc] = 0.0f;

#pragma unroll
        for (int ks = 0; ks < 8; ks++) {
            uint32_t b0[4], b1[4], a0[4], a1[4];
            LDSM_X4(b0[0], b0[1], b0[2], b0[3], bu + bOff[0] + (((ks * 2 + kh) ^ bRx[0]) << 4));
            LDSM_X4(b1[0], b1[1], b1[2], b1[3], bu + bOff[1] + (((ks * 2 + kh) ^ bRx[1]) << 4));
            LDSM_X4(a0[0], a0[1], a0[2], a0[3], aAddr[0] + (((ks * 2 + kh) ^ aRx[0]) << 4));
            LDSM_X4(a1[0], a1[1], a1[2], a1[3], aAddr[1] + (((ks * 2 + kh) ^ aRx[1]) << 4));
            MMA16816(acc[0][0], a0[0], a0[1], a0[2], a0[3], b0[0], b0[2]);
            MMA16816(acc[0][1], a0[0], a0[1], a0[2], a0[3], b0[1], b0[3]);
            MMA16816(acc[0][2], a0[0], a0[1], a0[2], a0[3], b1[0], b1[2]);
            MMA16816(acc[0][3], a0[0], a0[1], a0[2], a0[3], b1[1], b1[3]);
            MMA16816(acc[1][0], a1[0], a1[1], a1[2], a1[3], b0[0], b0[2]);
            MMA16816(acc[1][1], a1[0], a1[1], a1[2], a1[3], b0[1], b0[3]);
            MMA16816(acc[1][2], a1[0], a1[1], a1[2], a1[3], b1[0], b1[2]);
            MMA16816(acc[1][3], a1[0], a1[1], a1[2], a1[3], b1[1], b1[3]);
        }

#pragma unroll
        for (int mt = 0; mt < 2; mt++) {
#pragma unroll
            for (int hh = 0; hh < 2; hh++) {
                int ri = mt * 2 + hh;
                float tmax = acc[mt][0][hh * 2];
                tmax = fmaxf(tmax, acc[mt][0][hh * 2 + 1]);
#pragma unroll
                for (int nt = 1; nt < 4; nt++) {
                    tmax = fmaxf(tmax, acc[mt][nt][hh * 2]);
                    tmax = fmaxf(tmax, acc[mt][nt][hh * 2 + 1]);
                }
                if (__builtin_expect(tmax > mrow[ri] - THRESH, 0)) {
                    float newm = fmaxf(mrow[ri], tmax);
                    prow[ri] *= __expf(mrow[ri] - newm);
                    int ml = myLbl[ri];
#pragma unroll
                    for (int nt = 0; nt < 4; nt++)
#pragma unroll
                        for (int e = 0; e < 2; e++) {
                            float v = acc[mt][nt][hh * 2 + e];
                            if (v > newm - THRESH) {
                                int col = t * 128 + wn * 32 + nt * 8 + (lane & 3) * 2 + e;
                                if ((int)sLbl[col] != ml) prow[ri] += __expf(v - newm);
                            }
                        }
                    mrow[ri] = newm;
                }
            }
        }

        CP_WAIT0();
        __syncthreads();
    }

#pragma unroll
    for (int mt = 0; mt < 2; mt++)
#pragma unroll
        for (int hh = 0; hh < 2; hh++) {
            int ri = mt * 2 + hh;
            float m_ = mrow[ri], p_ = prow[ri];
#pragma unroll
            for (int off = 1; off <= 2; off <<= 1) {
                float om = __shfl_xor_sync(0xffffffffu, m_, off);
                float op = __shfl_xor_sync(0xffffffffu, p_, off);
                float M = fmaxf(m_, om);
                p_ = p_ * expf(m_ - M) + op * expf(om - M);
                m_ = M;
            }
            if ((lane & 3) == 0) {
                int rowloc = wm * 32 + mt * 16 + hh * 8 + (lane >> 2);
                s_red[rowloc][wn] = make_float2(m_, p_);
            }
        }
    __syncthreads();
    if (tid < 128) {
        float2 q0 = s_red[tid][0], q1 = s_red[tid][1];
        float2 q2 = s_red[tid][2], q3 = s_red[tid][3];
        float M = fmaxf(fmaxf(q0.x, q1.x), fmaxf(q2.x, q3.x));
        float P = q0.y * expf(q0.x - M) + q1.y * expf(q1.x - M)
                + q2.y * expf(q2.x - M) + q3.y * expf(q3.x - M);
        g_pm[(size_t)qd * MD + i0 + tid] = make_float2(M, P);
    }

    // -------- tail: last CTA reduces g_pm -> out (flag!=0 path) --------
    __shared__ int s_last;
    __threadfence();
    __syncthreads();
    if (tid == 0) s_last = (atomicAdd(&g_exdone, 1) == EX_CTAS - 1);
    __syncthreads();
    if (s_last) {
        __shared__ float s_pc[NCLS];
        __shared__ float ss[16], sc2[16];
        if (tid < NCLS) s_pc[tid] = (float)(g_hist[tid] - 1);
        __syncthreads();
        float sum = 0.0f, cnt2 = 0.0f;
        for (int i = tid; i < MD; i += 512) {
            float iou = ious[i];
            int l = labels[i];
            l = l < 0 ? 0 : (l >= NCLS ? NCLS - 1 : l);
            if (iou >= 0.5f) {
                float2 a = g_pm[i], b = g_pm[MD + i];
                float2 c = g_pm[2 * MD + i], d = g_pm[3 * MD + i];
                float M = fmaxf(fmaxf(a.x, b.x), fmaxf(c.x, d.x));
                float ns = a.y * expf(a.x - M) + b.y * expf(b.x - M)
                         + c.y * expf(c.x - M) + d.y * expf(d.x - M);
                sum += ns / s_pc[l];
                cnt2 += 1.0f;
            }
        }
#pragma unroll
        for (int off = 16; off > 0; off >>= 1) {
            sum  += __shfl_xor_sync(0xffffffffu, sum, off);
            cnt2 += __shfl_xor_sync(0xffffffffu, cnt2, off);
        }
        if ((tid & 31) == 0) { ss[tid >> 5] = sum; sc2[tid >> 5] = cnt2; }
        __syncthreads();
        if (tid == 0) {
            float S = 0.0f, C = 0.0f;
#pragma unroll
            for (int w = 0; w < 16; w++) { S += ss[w]; C += sc2[w]; }
            out[0] = S / C;
        }
    }
}

// ---------------------------------------------------------------- launch
extern "C" void kernel_launch(void* const* d_in, const int* in_sizes, int n_in,
                              void* d_out, int out_size) {
    const float* feat   = (const float*)d_in[0];
    const int*   labels = (const int*)  d_in[1];
    const float* ious   = (const float*)d_in[2];
    float*       out    = (float*)d_out;
    (void)in_sizes; (void)n_in; (void)out_size;

    const int smem_p1 = 66560;
    const int smem_ex = 98304 + 2048;
    cudaFuncSetAttribute(k_phase1, cudaFuncAttributeMaxDynamicSharedMemorySize, smem_p1);
    cudaFuncSetAttribute(k_exact,  cudaFuncAttributeMaxDynamicSharedMemorySize, smem_ex);

    k_prep<<<MD * KD / (256 * 8), 256>>>(feat, labels);
    k_phase1<<<P1_CTAS, 256, smem_p1>>>(labels, ious, out);
    k_exact<<<EX_CTAS, 512, smem_ex>>>(labels, ious, out);
}

// round 15
// speedup vs baseline: 1.1730x; 1.1730x over previous
#include <cuda_runtime.h>
#include <cuda_bf16.h>
#include <math.h>
#include <stdint.h>

// ============================================================================
// GraphCut loss, R15: 3 launches. k_phase1 reverted to the proven R13 body
// (R14's fused tail pushed the 85-reg-capped hot kernel into spills: 45->55us).
// The finalize is folded into k_exact instead (cold kernel, 64-reg cap set by
// its own MMA mainloop):
//   flag==0 -> k_exact CTA0 runs the cheap exact-zero reduction and writes out;
//              other CTAs return immediately.
//   flag!=0 -> full exact fallback; last CTA (ticket) reduces g_pm -> out.
// Exactness: all off-diag s_ij <= seed-109 => every reference exp underflows
// to exact fp32 zero (exp(x)==0 for x<=-105); violations -> exact fallback.
// ============================================================================

#define MD 8192
#define KD 128
#define NCLS 20
#define NBLK 64
#define NQ 2048
#define NTILES (NQ / 128)
#define THRESH 105.0f
#define SLACK 109.0f

#define P1_CTAS 444
#define P1_PER 9                 // 444*9 + 164 = 4160
#define P1_EXTRA 164
#define EX_CTAS 256

__device__ __align__(16) __nv_bfloat16 g_featB[(size_t)MD * KD];  // 2MB, *sqrt(5)
__device__ float  g_thr[MD];      // seed_i - SLACK
__device__ int    g_flagcnt;
__device__ float2 g_pm[4 * MD];   // fallback partials
__device__ int    g_hist[NCLS];
__device__ int    g_exdone;

// ---------------------------------------------------------------- helpers
__device__ __forceinline__ uint32_t smem_u32(const void* p) {
    uint32_t a;
    asm("{ .reg .u64 t; cvta.to.shared.u64 t, %1; cvt.u32.u64 %0, t; }" : "=r"(a) : "l"(p));
    return a;
}
#define CP_ASYNC16(dst, src) \
    asm volatile("cp.async.cg.shared.global [%0], [%1], 16;" :: "r"(dst), "l"(src) : "memory")
#define CP_COMMIT() asm volatile("cp.async.commit_group;" ::: "memory")
#define CP_WAIT0()  asm volatile("cp.async.wait_group 0;" ::: "memory")
#define LDSM_X4(r0, r1, r2, r3, a) \
    asm volatile("ldmatrix.sync.aligned.m8n8.x4.shared.b16 {%0,%1,%2,%3}, [%4];" \
                 : "=r"(r0), "=r"(r1), "=r"(r2), "=r"(r3) : "r"(a))
#define MMA16816(c, a0, a1, a2, a3, b0, b1) \
    asm volatile("mma.sync.aligned.m16n8k16.row.col.f32.bf16.bf16.f32 " \
                 "{%0,%1,%2,%3},{%4,%5,%6,%7},{%8,%9},{%0,%1,%2,%3};" \
                 : "+f"((c)[0]), "+f"((c)[1]), "+f"((c)[2]), "+f"((c)[3]) \
                 : "r"(a0), "r"(a1), "r"(a2), "r"(a3), "r"(b0), "r"(b1))

// --------------------------- prep: convert + seeds + hist + zeroing
__global__ void k_prep(const float* __restrict__ feat,
                       const int* __restrict__ labels) {
    __shared__ int sh[NCLS];
    const float SC = 2.23606797749979f;   // sqrt(1/0.2)
    int tid = threadIdx.x;
    int bid = blockIdx.x;
    int i = (bid * 256 + tid) * 8;

    if (bid == 0) {
        if (tid < NCLS) g_hist[tid] = 0;
        if (tid == 0) { g_flagcnt = 0; g_exdone = 0; }
    }

    float4 f0 = *(const float4*)&feat[i];
    float4 f1 = *(const float4*)&feat[i + 4];
    union { __nv_bfloat16 h[8]; uint4 u; } U;
    U.h[0] = __float2bfloat16(f0.x * SC); U.h[1] = __float2bfloat16(f0.y * SC);
    U.h[2] = __float2bfloat16(f0.z * SC); U.h[3] = __float2bfloat16(f0.w * SC);
    U.h[4] = __float2bfloat16(f1.x * SC); U.h[5] = __float2bfloat16(f1.y * SC);
    U.h[6] = __float2bfloat16(f1.z * SC); U.h[7] = __float2bfloat16(f1.w * SC);
    *(uint4*)&g_featB[i] = U.u;
    float s = 0.0f;
#pragma unroll
    for (int e = 0; e < 8; e++) {
        float v = __bfloat162float(U.h[e]);
        s = fmaf(v, v, s);
    }
#pragma unroll
    for (int off = 1; off <= 8; off <<= 1)
        s += __shfl_xor_sync(0xffffffffu, s, off);
    if ((tid & 15) == 0)
        g_thr[bid * 16 + (tid >> 4)] = s - SLACK;

    // CTAs 1..8 build the label histogram (avoid CTA0's zeroing race).
    if (bid >= 1 && bid <= 8) {
        if (tid < NCLS) sh[tid] = 0;
        __syncthreads();
        int4 L = ((const int4*)labels)[(bid - 1) * 256 + tid];
        int l0 = L.x, l1 = L.y, l2 = L.z, l3 = L.w;
        l0 = l0 < 0 ? 0 : (l0 >= NCLS ? NCLS - 1 : l0);
        l1 = l1 < 0 ? 0 : (l1 >= NCLS ? NCLS - 1 : l1);
        l2 = l2 < 0 ? 0 : (l2 >= NCLS ? NCLS - 1 : l2);
        l3 = l3 < 0 ? 0 : (l3 >= NCLS ? NCLS - 1 : l3);
        atomicAdd(&sh[l0], 1); atomicAdd(&sh[l1], 1);
        atomicAdd(&sh[l2], 1); atomicAdd(&sh[l3], 1);
        __syncthreads();
        if (tid < NCLS) atomicAdd(&g_hist[tid], sh[tid]);
    }
}

// ---------------------------------------------------------------- tile fills
__device__ __forceinline__ void fillA256(char* A_s, int row0, int tid) {
#pragma unroll
    for (int v = 0; v < 8; v++) {
        int idx = tid + v * 256;
        int row = idx >> 4, c16 = idx & 15;
        uint4 val = *(const uint4*)&g_featB[(size_t)(row0 + row) * KD + c16 * 8];
        *(uint4*)(A_s + row * 256 + ((c16 ^ (row & 7)) << 4)) = val;
    }
}
__device__ __forceinline__ void fillB64_async(uint32_t bu, int row0, int tid) {
#pragma unroll
    for (int v = 0; v < 4; v++) {
        int idx = tid + v * 256;
        int row = idx >> 4, c16 = idx & 15;
        CP_ASYNC16(bu + row * 256 + ((c16 ^ (row & 7)) << 4),
                   &g_featB[(size_t)(row0 + row) * KD + c16 * 8]);
    }
}
__device__ __forceinline__ void fillA512(char* A_s, int row0, int tid) {
#pragma unroll
    for (int v = 0; v < 4; v++) {
        int idx = tid + v * 512;
        int row = idx >> 4, c16 = idx & 15;
        uint4 val = *(const uint4*)&g_featB[(size_t)(row0 + row) * KD + c16 * 8];
        *(uint4*)(A_s + row * 256 + ((c16 ^ (row & 7)) << 4)) = val;
    }
}
__device__ __forceinline__ void fillB128_async(uint32_t bu, int row0, int tid) {
#pragma unroll
    for (int v = 0; v < 4; v++) {
        int idx = tid + v * 512;
        int row = idx >> 4, c16 = idx & 15;
        CP_ASYNC16(bu + row * 256 + ((c16 ^ (row & 7)) << 4),
                   &g_featB[(size_t)(row0 + row) * KD + c16 * 8]);
    }
}

// ---------------------------------------------------------------- phase 1 (R13 body, unchanged)
__global__ void __launch_bounds__(256, 3) k_phase1() {
    extern __shared__ char dsm[];
    char*  A_s   = dsm;                       // 32KB
    char*  B_s   = dsm + 32768;               // 2 x 16KB
    float* thrC  = (float*)(dsm + 65536);     // 2 x 64 floats
    float* sThrR = (float*)(dsm + 66048);     // 128 floats
    uint32_t A_u = smem_u32(A_s);
    uint32_t B_u = smem_u32(B_s);
    uint32_t thrC_u = smem_u32(thrC);

    int tid = threadIdx.x, lane = tid & 31, wid = tid >> 5;
    int wm = wid >> 1, wn = wid & 1;          // 4 x 2 warp grid
    int c = blockIdx.x;
    int base = c * P1_PER + (c < P1_EXTRA ? c : P1_EXTRA);
    int cnt  = P1_PER + (c < P1_EXTRA ? 1 : 0);

    int t0 = base >> 1;
    int h  = base & 1;
    int I = 0, tt = t0;
    while (tt >= NBLK - I) { tt -= NBLK - I; I++; }
    int J = I + tt;

    fillA256(A_s, I * 128, tid);
    if (tid < 128) sThrR[tid] = g_thr[I * 128 + tid];
    fillB64_async(B_u, J * 128 + h * 64, tid);
    if (tid < 16) CP_ASYNC16(thrC_u + tid * 16, &g_thr[J * 128 + h * 64 + tid * 4]);
    CP_COMMIT();

    int q  = lane >> 3;
    int kh = q >> 1;
    uint32_t aAddr[2]; int aRx[2];
#pragma unroll
    for (int mt = 0; mt < 2; mt++) {
        int row = wm * 32 + mt * 16 + (lane & 7) + ((q & 1) << 3);
        aAddr[mt] = A_u + row * 256;
        aRx[mt]   = row & 7;
    }
    uint32_t bOff[2]; int bRx[2];
#pragma unroll
    for (int bt = 0; bt < 2; bt++) {
        int row = wn * 32 + bt * 16 + (lane & 7) + ((q & 1) << 3);
        bOff[bt] = row * 256;
        bRx[bt]  = row & 7;
    }

    CP_WAIT0();
    __syncthreads();

    for (int it = 0; it < cnt; it++) {
        int In = I, Jn = J, hn = h ^ 1;
        if (hn == 0) {
            Jn = J + 1;
            if (Jn == NBLK) { In = I + 1; Jn = In; }
        }

        if (it + 1 < cnt) {
            uint32_t bu = B_u + ((it + 1) & 1) * 16384;
            fillB64_async(bu, Jn * 128 + hn * 64, tid);
            if (tid < 16)
                CP_ASYNC16(thrC_u + ((it + 1) & 1) * 256 + tid * 16,
                           &g_thr[Jn * 128 + hn * 64 + tid * 4]);
            CP_COMMIT();
        }

        uint32_t bu = B_u + (it & 1) * 16384;
        float acc[2][4][4];
#pragma unroll
        for (int a = 0; a < 2; a++)
#pragma unroll
            for (int b = 0; b < 4; b++)
#pragma unroll
                for (int cc = 0; cc < 4; cc++) acc[a][b][cc] = 0.0f;

#pragma unroll
        for (int ks = 0; ks < 8; ks++) {
            uint32_t b0[4], b1[4], a0[4], a1[4];
            LDSM_X4(b0[0], b0[1], b0[2], b0[3], bu + bOff[0] + (((ks * 2 + kh) ^ bRx[0]) << 4));
            LDSM_X4(b1[0], b1[1], b1[2], b1[3], bu + bOff[1] + (((ks * 2 + kh) ^ bRx[1]) << 4));
            LDSM_X4(a0[0], a0[1], a0[2], a0[3], aAddr[0] + (((ks * 2 + kh) ^ aRx[0]) << 4));
            LDSM_X4(a1[0], a1[1], a1[2], a1[3], aAddr[1] + (((ks * 2 + kh) ^ aRx[1]) << 4));
            MMA16816(acc[0][0], a0[0], a0[1], a0[2], a0[3], b0[0], b0[2]);
            MMA16816(acc[0][1], a0[0], a0[1], a0[2], a0[3], b0[1], b0[3]);
            MMA16816(acc[0][2], a0[0], a0[1], a0[2], a0[3], b1[0], b1[2]);
            MMA16816(acc[0][3], a0[0], a0[1], a0[2], a0[3], b1[1], b1[3]);
            MMA16816(acc[1][0], a1[0], a1[1], a1[2], a1[3], b0[0], b0[2]);
            MMA16816(acc[1][1], a1[0], a1[1], a1[2], a1[3], b0[1], b0[3]);
            MMA16816(acc[1][2], a1[0], a1[1], a1[2], a1[3], b1[0], b1[2]);
            MMA16816(acc[1][3], a1[0], a1[1], a1[2], a1[3], b1[1], b1[3]);
        }

        {
            int diag = (I == J);
            int cbase = h * 64;
            const float* tC = thrC + (it & 1) * 64;
            bool f = false;
#pragma unroll
            for (int mt = 0; mt < 2; mt++)
#pragma unroll
                for (int hh = 0; hh < 2; hh++) {
                    int rl = wm * 32 + mt * 16 + hh * 8 + (lane >> 2);
                    float tr = sThrR[rl];
#pragma unroll
                    for (int nt = 0; nt < 4; nt++)
#pragma unroll
                        for (int e = 0; e < 2; e++) {
                            int cl = wn * 32 + nt * 8 + (lane & 3) * 2 + e;
                            float v = acc[mt][nt][hh * 2 + e];
                            bool ex = diag && (rl == cbase + cl);
                            f |= (!ex) && ((v > tr) || (v > tC[cl]));
                        }
                }
            if (__any_sync(0xffffffffu, f) && lane == 0) atomicAdd(&g_flagcnt, 1);
        }

        CP_WAIT0();
        __syncthreads();

        if (it + 1 < cnt && In != I) {
            fillA256(A_s, In * 128, tid);
            if (tid < 128) sThrR[tid] = g_thr[In * 128 + tid];
            __syncthreads();
        }
        I = In; J = Jn; h = hn;
    }
}

// ----------------- exact fallback + fused finalize (both paths)
__global__ void __launch_bounds__(512, 2)
k_exact(const int* __restrict__ labels, const float* __restrict__ ious,
        float* __restrict__ out) {
    int tid  = threadIdx.x;

    if (g_flagcnt == 0) {
        // Fast path: all neg-sums are exactly 0. CTA0 computes the output.
        if (blockIdx.x != 0) return;
        __shared__ float s_pc[NCLS];
        __shared__ float ss[16], sc2[16];
        if (tid < NCLS) s_pc[tid] = (float)(g_hist[tid] - 1);
        __syncthreads();
        float sum = 0.0f, cnt2 = 0.0f;
#pragma unroll
        for (int v = tid; v < MD / 4; v += 512) {
            float4 io = ((const float4*)ious)[v];
            int4 L = ((const int4*)labels)[v];
            float iv[4] = {io.x, io.y, io.z, io.w};
            int lv[4] = {L.x, L.y, L.z, L.w};
#pragma unroll
            for (int e = 0; e < 4; e++) {
                int l = lv[e];
                l = l < 0 ? 0 : (l >= NCLS ? NCLS - 1 : l);
                if (iv[e] >= 0.5f) {
                    sum += 0.0f / s_pc[l];   // exact: ns==0; 0/0 -> nan as ref
                    cnt2 += 1.0f;
                }
            }
        }
#pragma unroll
        for (int off = 16; off > 0; off >>= 1) {
            sum  += __shfl_xor_sync(0xffffffffu, sum, off);
            cnt2 += __shfl_xor_sync(0xffffffffu, cnt2, off);
        }
        if ((tid & 31) == 0) { ss[tid >> 5] = sum; sc2[tid >> 5] = cnt2; }
        __syncthreads();
        if (tid == 0) {
            float S = 0.0f, C = 0.0f;
#pragma unroll
            for (int w = 0; w < 16; w++) { S += ss[w]; C += sc2[w]; }
            out[0] = S / C;
        }
        return;
    }

    // ---- full exact fallback ----
    extern __shared__ char dsm[];
    __shared__ float2 s_red[128][4];
    __shared__ float  s_seed[128];

    char* A_s  = dsm;
    char* B_s  = dsm + 32768;
    unsigned char* sLbl = (unsigned char*)(dsm + 98304);
    uint32_t A_u = smem_u32(A_s);
    uint32_t B_u = smem_u32(B_s);

    int lane = tid & 31;
    int wid  = tid >> 5;
    int wm   = wid >> 2;
    int wn   = wid & 3;
    int r    = blockIdx.x >> 2;
    int qd   = blockIdx.x & 3;
    int i0   = r * 128;
    int j0   = qd * NQ;

    fillA512(A_s, i0, tid);
    fillB128_async(B_u, j0, tid);
    CP_COMMIT();
    {
        int4 L = ((const int4*)(labels + j0))[tid];
        ((uint32_t*)sLbl)[tid] = (uint32_t)(L.x & 255) | ((uint32_t)(L.y & 255) << 8)
                               | ((uint32_t)(L.z & 255) << 16) | ((uint32_t)(L.w & 255) << 24);
    }
    {
        int sr = tid >> 2, sq = tid & 3;
        const uint4* rp = (const uint4*)&g_featB[(size_t)(i0 + sr) * KD + sq * 32];
        float sacc = 0.0f;
#pragma unroll
        for (int g = 0; g < 4; g++) {
            uint4 u = rp[g];
            uint32_t w[4] = {u.x, u.y, u.z, u.w};
#pragma unroll
            for (int e = 0; e < 4; e++) {
                float lo = __uint_as_float(w[e] << 16);
                float hi = __uint_as_float(w[e] & 0xffff0000u);
                sacc = fmaf(lo, lo, sacc);
                sacc = fmaf(hi, hi, sacc);
            }
        }
        sacc += __shfl_xor_sync(0xffffffffu, sacc, 1);
        sacc += __shfl_xor_sync(0xffffffffu, sacc, 2);
        if (sq == 0) s_seed[sr] = sacc;
    }

    int myLbl[4];
#pragma unroll
    for (int mt = 0; mt < 2; mt++)
#pragma unroll
        for (int hh = 0; hh < 2; hh++)
            myLbl[mt * 2 + hh] = labels[i0 + wm * 32 + mt * 16 + hh * 8 + (lane >> 2)];

    int q  = lane >> 3;
    int kh = q >> 1;
    uint32_t aAddr[2]; int aRx[2];
#pragma unroll
    for (int mt = 0; mt < 2; mt++) {
        int row = wm * 32 + mt * 16 + (lane & 7) + ((q & 1) << 3);
        aAddr[mt] = A_u + row * 256;
        aRx[mt]   = row & 7;
    }
    uint32_t bOff[2]; int bRx[2];
#pragma unroll
    for (int bt = 0; bt < 2; bt++) {
        int row = wn * 32 + bt * 16 + (lane & 7) + ((q & 1) << 3);
        bOff[bt] = row * 256;
        bRx[bt]  = row & 7;
    }

    CP_WAIT0();
    __syncthreads();

    float mrow[4], prow[4];
#pragma unroll
    for (int mt = 0; mt < 2; mt++)
#pragma unroll
        for (int hh = 0; hh < 2; hh++) {
            mrow[mt * 2 + hh] = s_seed[wm * 32 + mt * 16 + hh * 8 + (lane >> 2)];
            prow[mt * 2 + hh] = 0.0f;
        }

    for (int t = 0; t < NTILES; t++) {
        if (t + 1 < NTILES) {
            fillB128_async(B_u + ((t + 1) & 1) * 32768, j0 + (t + 1) * 128, tid);
            CP_COMMIT();
        }

        uint32_t bu = B_u + (t & 1) * 32768;
        float acc[2][4][4];
#pragma unroll
        for (int a = 0; a < 2; a++)
#pragma unroll
            for (int b = 0; b < 4; b++)
#pragma unroll
                for (int cc = 0; cc < 4; cc++) acc[a][b][cc] = 0.0f;

#pragma unroll
        for (int ks = 0; ks < 8; ks++) {
            uint32_t b0[4], b1[4], a0[4], a1[4];
            LDSM_X4(b0[0], b0[1], b0[2], b0[3], bu + bOff[0] + (((ks * 2 + kh) ^ bRx[0]) << 4));
            LDSM_X4(b1[0], b1[1], b1[2], b1[3], bu + bOff[1] + (((ks * 2 + kh) ^ bRx[1]) << 4));
            LDSM_X4(a0[0], a0[1], a0[2], a0[3], aAddr[0] + (((ks * 2 + kh) ^ aRx[0]) << 4));
            LDSM_X4(a1[0], a1[1], a1[2], a1[3], aAddr[1] + (((ks * 2 + kh) ^ aRx[1]) << 4));
            MMA16816(acc[0][0], a0[0], a0[1], a0[2], a0[3], b0[0], b0[2]);
            MMA16816(acc[0][1], a0[0], a0[1], a0[2], a0[3], b0[1], b0[3]);
            MMA16816(acc[0][2], a0[0], a0[1], a0[2], a0[3], b1[0], b1[2]);
            MMA16816(acc[0][3], a0[0], a0[1], a0[2], a0[3], b1[1], b1[3]);
            MMA16816(acc[1][0], a1[0], a1[1], a1[2], a1[3], b0[0], b0[2]);
            MMA16816(acc[1][1], a1[0], a1[1], a1[2], a1[3], b0[1], b0[3]);
            MMA16816(acc[1][2], a1[0], a1[1], a1[2], a1[3], b1[0], b1[2]);
            MMA16816(acc[1][3], a1[0], a1[1], a1[2], a1[3], b1[1], b1[3]);
        }

#pragma unroll
        for (int mt = 0; mt < 2; mt++) {
#pragma unroll
            for (int hh = 0; hh < 2; hh++) {
                int ri = mt * 2 + hh;
                float tmax = acc[mt][0][hh * 2];
                tmax = fmaxf(tmax, acc[mt][0][hh * 2 + 1]);
#pragma unroll
                for (int nt = 1; nt < 4; nt++) {
                    tmax = fmaxf(tmax, acc[mt][nt][hh * 2]);
                    tmax = fmaxf(tmax, acc[mt][nt][hh * 2 + 1]);
                }
                if (__builtin_expect(tmax > mrow[ri] - THRESH, 0)) {
                    float newm = fmaxf(mrow[ri], tmax);
                    prow[ri] *= __expf(mrow[ri] - newm);
                    int ml = myLbl[ri];
#pragma unroll
                    for (int nt = 0; nt < 4; nt++)
#pragma unroll
                        for (int e = 0; e < 2; e++) {
                            float v = acc[mt][nt][hh * 2 + e];
                            if (v > newm - THRESH) {
                                int col = t * 128 + wn * 32 + nt * 8 + (lane & 3) * 2 + e;
                                if ((int)sLbl[col] != ml) prow[ri] += __expf(v - newm);
                            }
                        }
                    mrow[ri] = newm;
                }
            }
        }

        CP_WAIT0();
        __syncthreads();
    }

#pragma unroll
    for (int mt = 0; mt < 2; mt++)
#pragma unroll
        for (int hh = 0; hh < 2; hh++) {
            int ri = mt * 2 + hh;
            float m_ = mrow[ri], p_ = prow[ri];
#pragma unroll
            for (int off = 1; off <= 2; off <<= 1) {
                float om = __shfl_xor_sync(0xffffffffu, m_, off);
                float op = __shfl_xor_sync(0xffffffffu, p_, off);
                float M = fmaxf(m_, om);
                p_ = p_ * expf(m_ - M) + op * expf(om - M);
                m_ = M;
            }
            if ((lane & 3) == 0) {
                int rowloc = wm * 32 + mt * 16 + hh * 8 + (lane >> 2);
                s_red[rowloc][wn] = make_float2(m_, p_);
            }
        }
    __syncthreads();
    if (tid < 128) {
        float2 q0 = s_red[tid][0], q1 = s_red[tid][1];
        float2 q2 = s_red[tid][2], q3 = s_red[tid][3];
        float M = fmaxf(fmaxf(q0.x, q1.x), fmaxf(q2.x, q3.x));
        float P = q0.y * expf(q0.x - M) + q1.y * expf(q1.x - M)
                + q2.y * expf(q2.x - M) + q3.y * expf(q3.x - M);
        g_pm[(size_t)qd * MD + i0 + tid] = make_float2(M, P);
    }

    // -------- tail: last CTA reduces g_pm -> out --------
    __shared__ int s_last;
    __threadfence();
    __syncthreads();
    if (tid == 0) s_last = (atomicAdd(&g_exdone, 1) == EX_CTAS - 1);
    __syncthreads();
    if (s_last) {
        __shared__ float s_pc[NCLS];
        __shared__ float ss[16], sc2[16];
        if (tid < NCLS) s_pc[tid] = (float)(g_hist[tid] - 1);
        __syncthreads();
        float sum = 0.0f, cnt2 = 0.0f;
        for (int i = tid; i < MD; i += 512) {
            float iou = ious[i];
            int l = labels[i];
            l = l < 0 ? 0 : (l >= NCLS ? NCLS - 1 : l);
            if (iou >= 0.5f) {
                float2 a = g_pm[i], b = g_pm[MD + i];
                float2 c = g_pm[2 * MD + i], d = g_pm[3 * MD + i];
                float M = fmaxf(fmaxf(a.x, b.x), fmaxf(c.x, d.x));
                float ns = a.y * expf(a.x - M) + b.y * expf(b.x - M)
                         + c.y * expf(c.x - M) + d.y * expf(d.x - M);
                sum += ns / s_pc[l];
                cnt2 += 1.0f;
            }
        }
#pragma unroll
        for (int off = 16; off > 0; off >>= 1) {
            sum  += __shfl_xor_sync(0xffffffffu, sum, off);
            cnt2 += __shfl_xor_sync(0xffffffffu, cnt2, off);
        }
        if ((tid & 31) == 0) { ss[tid >> 5] = sum; sc2[tid >> 5] = cnt2; }
        __syncthreads();
        if (tid == 0) {
            float S = 0.0f, C = 0.0f;
#pragma unroll
            for (int w = 0; w < 16; w++) { S += ss[w]; C += sc2[w]; }
            out[0] = S / C;
        }
    }
}

// ---------------------------------------------------------------- launch
extern "C" void kernel_launch(void* const* d_in, const int* in_sizes, int n_in,
                              void* d_out, int out_size) {
    const float* feat   = (const float*)d_in[0];
    const int*   labels = (const int*)  d_in[1];
    const float* ious   = (const float*)d_in[2];
    float*       out    = (float*)d_out;
    (void)in_sizes; (void)n_in; (void)out_size;

    const int smem_p1 = 66560;
    const int smem_ex = 98304 + 2048;
    cudaFuncSetAttribute(k_phase1, cudaFuncAttributeMaxDynamicSharedMemorySize, smem_p1);
    cudaFuncSetAttribute(k_exact,  cudaFuncAttributeMaxDynamicSharedMemorySize, smem_ex);

    k_prep<<<MD * KD / (256 * 8), 256>>>(feat, labels);
    k_phase1<<<P1_CTAS, 256, smem_p1>>>();
    k_exact<<<EX_CTAS, 512, smem_ex>>>(labels, ious, out);
}

// round 16
// speedup vs baseline: 1.4207x; 1.2112x over previous
#include <cuda_runtime.h>
#include <cuda_fp16.h>
#include <math.h>
#include <stdint.h>

// ============================================================================
// GraphCut loss, R16: verification scan with fp16-ACCUM MMA (2x tensor rate).
// Pipeline (R13 structure): k_prep (convert fp16 + seeds + hist + zero) ->
// k_phase1 (444 CTAs, 3/SM, 4160 128x64 half-tiles, f16xf16+f16 mma, half2
// threshold compares) -> k_exact (exact fallback, f32-accum fp16 mma, no-op
// when flag==0) -> k_fsum (reduce + final divide).
// Exactness: verified v <= seed-112 implies true fp32 s_ij <= rowmax-105
// (fp16 accum err <~2, quant err <~1, threshold rounded down), and fp32
// exp(x)==0 exactly for x<=-105 => every reference term is exactly 0.
// Any violation -> g_flagcnt -> exact fallback recomputes everything.
// ============================================================================

#define MD 8192
#define KD 128
#define NCLS 20
#define NBLK 64
#define NQ 2048
#define NTILES (NQ / 128)
#define THRESH 105.0f
#define SLACK 112.0f

#define P1_CTAS 444
#define P1_PER 9                 // 444*9 + 164 = 4160
#define P1_EXTRA 164

__device__ __align__(16) __half g_featH[(size_t)MD * KD];  // 2MB, *sqrt(5)
__device__ __half g_thrH[MD];     // half(seed_i - SLACK), rounded down
__device__ int    g_flagcnt;
__device__ float2 g_pm[4 * MD];   // fallback partials
__device__ int    g_hist[NCLS];
__device__ float  g_sum, g_cnt;
__device__ int    g_done;

// ---------------------------------------------------------------- helpers
__device__ __forceinline__ uint32_t smem_u32(const void* p) {
    uint32_t a;
    asm("{ .reg .u64 t; cvta.to.shared.u64 t, %1; cvt.u32.u64 %0, t; }" : "=r"(a) : "l"(p));
    return a;
}
#define CP_ASYNC16(dst, src) \
    asm volatile("cp.async.cg.shared.global [%0], [%1], 16;" :: "r"(dst), "l"(src) : "memory")
#define CP_COMMIT() asm volatile("cp.async.commit_group;" ::: "memory")
#define CP_WAIT0()  asm volatile("cp.async.wait_group 0;" ::: "memory")
#define LDSM_X4(r0, r1, r2, r3, a) \
    asm volatile("ldmatrix.sync.aligned.m8n8.x4.shared.b16 {%0,%1,%2,%3}, [%4];" \
                 : "=r"(r0), "=r"(r1), "=r"(r2), "=r"(r3) : "r"(a))
// fp16-accum MMA (2x rate): D(f16) = A(f16)*B(f16) + C(f16)
#define MMA16816H(c, a0, a1, a2, a3, b0, b1) \
    asm volatile("mma.sync.aligned.m16n8k16.row.col.f16.f16.f16.f16 " \
                 "{%0,%1},{%2,%3,%4,%5},{%6,%7},{%0,%1};" \
                 : "+r"((c)[0]), "+r"((c)[1]) \
                 : "r"(a0), "r"(a1), "r"(a2), "r"(a3), "r"(b0), "r"(b1))
// fp32-accum MMA for exact fallback
#define MMA16816F(c, a0, a1, a2, a3, b0, b1) \
    asm volatile("mma.sync.aligned.m16n8k16.row.col.f32.f16.f16.f32 " \
                 "{%0,%1,%2,%3},{%4,%5,%6,%7},{%8,%9},{%0,%1,%2,%3};" \
                 : "+f"((c)[0]), "+f"((c)[1]), "+f"((c)[2]), "+f"((c)[3]) \
                 : "r"(a0), "r"(a1), "r"(a2), "r"(a3), "r"(b0), "r"(b1))

// --------------------------- prep: convert + seeds + hist + zeroing
__global__ void k_prep(const float* __restrict__ feat,
                       const int* __restrict__ labels) {
    __shared__ int sh[NCLS];
    const float SC = 2.23606797749979f;   // sqrt(1/0.2)
    int tid = threadIdx.x;
    int bid = blockIdx.x;
    int i = (bid * 256 + tid) * 8;

    if (bid == 0) {
        if (tid < NCLS) g_hist[tid] = 0;
        if (tid == 0) { g_flagcnt = 0; g_sum = 0.0f; g_cnt = 0.0f; g_done = 0; }
    }

    float4 f0 = *(const float4*)&feat[i];
    float4 f1 = *(const float4*)&feat[i + 4];
    union { __half h[8]; uint4 u; } U;
    U.h[0] = __float2half(f0.x * SC); U.h[1] = __float2half(f0.y * SC);
    U.h[2] = __float2half(f0.z * SC); U.h[3] = __float2half(f0.w * SC);
    U.h[4] = __float2half(f1.x * SC); U.h[5] = __float2half(f1.y * SC);
    U.h[6] = __float2half(f1.z * SC); U.h[7] = __float2half(f1.w * SC);
    *(uint4*)&g_featH[i] = U.u;
    float s = 0.0f;
#pragma unroll
    for (int e = 0; e < 8; e++) {
        float v = __half2float(U.h[e]);
        s = fmaf(v, v, s);
    }
#pragma unroll
    for (int off = 1; off <= 8; off <<= 1)
        s += __shfl_xor_sync(0xffffffffu, s, off);
    if ((tid & 15) == 0)
        g_thrH[bid * 16 + (tid >> 4)] = __float2half_rd(s - SLACK);  // round down: conservative

    // CTAs 1..8 build the label histogram (avoid CTA0's zeroing race).
    if (bid >= 1 && bid <= 8) {
        if (tid < NCLS) sh[tid] = 0;
        __syncthreads();
        int4 L = ((const int4*)labels)[(bid - 1) * 256 + tid];
        int l0 = L.x, l1 = L.y, l2 = L.z, l3 = L.w;
        l0 = l0 < 0 ? 0 : (l0 >= NCLS ? NCLS - 1 : l0);
        l1 = l1 < 0 ? 0 : (l1 >= NCLS ? NCLS - 1 : l1);
        l2 = l2 < 0 ? 0 : (l2 >= NCLS ? NCLS - 1 : l2);
        l3 = l3 < 0 ? 0 : (l3 >= NCLS ? NCLS - 1 : l3);
        atomicAdd(&sh[l0], 1); atomicAdd(&sh[l1], 1);
        atomicAdd(&sh[l2], 1); atomicAdd(&sh[l3], 1);
        __syncthreads();
        if (tid < NCLS) atomicAdd(&g_hist[tid], sh[tid]);
    }
}

// ---------------------------------------------------------------- tile fills
__device__ __forceinline__ void fillA256(char* A_s, int row0, int tid) {
#pragma unroll
    for (int v = 0; v < 8; v++) {
        int idx = tid + v * 256;
        int row = idx >> 4, c16 = idx & 15;
        uint4 val = *(const uint4*)&g_featH[(size_t)(row0 + row) * KD + c16 * 8];
        *(uint4*)(A_s + row * 256 + ((c16 ^ (row & 7)) << 4)) = val;
    }
}
__device__ __forceinline__ void fillB64_async(uint32_t bu, int row0, int tid) {
#pragma unroll
    for (int v = 0; v < 4; v++) {
        int idx = tid + v * 256;
        int row = idx >> 4, c16 = idx & 15;
        CP_ASYNC16(bu + row * 256 + ((c16 ^ (row & 7)) << 4),
                   &g_featH[(size_t)(row0 + row) * KD + c16 * 8]);
    }
}
__device__ __forceinline__ void fillA512(char* A_s, int row0, int tid) {
#pragma unroll
    for (int v = 0; v < 4; v++) {
        int idx = tid + v * 512;
        int row = idx >> 4, c16 = idx & 15;
        uint4 val = *(const uint4*)&g_featH[(size_t)(row0 + row) * KD + c16 * 8];
        *(uint4*)(A_s + row * 256 + ((c16 ^ (row & 7)) << 4)) = val;
    }
}
__device__ __forceinline__ void fillB128_async(uint32_t bu, int row0, int tid) {
#pragma unroll
    for (int v = 0; v < 4; v++) {
        int idx = tid + v * 512;
        int row = idx >> 4, c16 = idx & 15;
        CP_ASYNC16(bu + row * 256 + ((c16 ^ (row & 7)) << 4),
                   &g_featH[(size_t)(row0 + row) * KD + c16 * 8]);
    }
}

// ---------------------------------------------------------------- phase 1
__global__ void __launch_bounds__(256, 3) k_phase1() {
    extern __shared__ char dsm[];
    char*   A_s    = dsm;                       // 32KB
    char*   B_s    = dsm + 32768;               // 2 x 16KB
    __half* thrC   = (__half*)(dsm + 65536);    // 2 x 64 halves (2 x 128B)
    __half* sThrRh = (__half*)(dsm + 65792);    // 128 halves
    uint32_t A_u = smem_u32(A_s);
    uint32_t B_u = smem_u32(B_s);
    uint32_t thrC_u = smem_u32(thrC);

    int tid = threadIdx.x, lane = tid & 31, wid = tid >> 5;
    int wm = wid >> 1, wn = wid & 1;            // 4 x 2 warp grid (32x32)
    int c = blockIdx.x;
    int base = c * P1_PER + (c < P1_EXTRA ? c : P1_EXTRA);
    int cnt  = P1_PER + (c < P1_EXTRA ? 1 : 0);

    int t0 = base >> 1;
    int h  = base & 1;
    int I = 0, tt = t0;
    while (tt >= NBLK - I) { tt -= NBLK - I; I++; }
    int J = I + tt;

    fillA256(A_s, I * 128, tid);
    if (tid < 128) sThrRh[tid] = g_thrH[I * 128 + tid];
    fillB64_async(B_u, J * 128 + h * 64, tid);
    if (tid < 8) CP_ASYNC16(thrC_u + tid * 16, &g_thrH[J * 128 + h * 64 + tid * 8]);
    CP_COMMIT();

    int q  = lane >> 3;
    int kh = q >> 1;
    uint32_t aAddr[2]; int aRx[2];
#pragma unroll
    for (int mt = 0; mt < 2; mt++) {
        int row = wm * 32 + mt * 16 + (lane & 7) + ((q & 1) << 3);
        aAddr[mt] = A_u + row * 256;
        aRx[mt]   = row & 7;
    }
    uint32_t bOff[2]; int bRx[2];
#pragma unroll
    for (int bt = 0; bt < 2; bt++) {
        int row = wn * 32 + bt * 16 + (lane & 7) + ((q & 1) << 3);
        bOff[bt] = row * 256;
        bRx[bt]  = row & 7;
    }

    CP_WAIT0();
    __syncthreads();

    for (int it = 0; it < cnt; it++) {
        int In = I, Jn = J, hn = h ^ 1;
        if (hn == 0) {
            Jn = J + 1;
            if (Jn == NBLK) { In = I + 1; Jn = In; }
        }

        if (it + 1 < cnt) {
            uint32_t bu = B_u + ((it + 1) & 1) * 16384;
            fillB64_async(bu, Jn * 128 + hn * 64, tid);
            if (tid < 8)
                CP_ASYNC16(thrC_u + ((it + 1) & 1) * 128 + tid * 16,
                           &g_thrH[Jn * 128 + hn * 64 + tid * 8]);
            CP_COMMIT();
        }

        uint32_t bu = B_u + (it & 1) * 16384;
        uint32_t acc[2][4][2];                  // f16 accum: half2 per reg
#pragma unroll
        for (int a = 0; a < 2; a++)
#pragma unroll
            for (int b = 0; b < 4; b++) { acc[a][b][0] = 0u; acc[a][b][1] = 0u; }

#pragma unroll
        for (int ks = 0; ks < 8; ks++) {
            uint32_t b0[4], b1[4], a0[4], a1[4];
            LDSM_X4(b0[0], b0[1], b0[2], b0[3], bu + bOff[0] + (((ks * 2 + kh) ^ bRx[0]) << 4));
            LDSM_X4(b1[0], b1[1], b1[2], b1[3], bu + bOff[1] + (((ks * 2 + kh) ^ bRx[1]) << 4));
            LDSM_X4(a0[0], a0[1], a0[2], a0[3], aAddr[0] + (((ks * 2 + kh) ^ aRx[0]) << 4));
            LDSM_X4(a1[0], a1[1], a1[2], a1[3], aAddr[1] + (((ks * 2 + kh) ^ aRx[1]) << 4));
            MMA16816H(acc[0][0], a0[0], a0[1], a0[2], a0[3], b0[0], b0[2]);
            MMA16816H(acc[0][1], a0[0], a0[1], a0[2], a0[3], b0[1], b0[3]);
            MMA16816H(acc[0][2], a0[0], a0[1], a0[2], a0[3], b1[0], b1[2]);
            MMA16816H(acc[0][3], a0[0], a0[1], a0[2], a0[3], b1[1], b1[3]);
            MMA16816H(acc[1][0], a1[0], a1[1], a1[2], a1[3], b0[0], b0[2]);
            MMA16816H(acc[1][1], a1[0], a1[1], a1[2], a1[3], b0[1], b0[3]);
            MMA16816H(acc[1][2], a1[0], a1[1], a1[2], a1[3], b1[0], b1[2]);
            MMA16816H(acc[1][3], a1[0], a1[1], a1[2], a1[3], b1[1], b1[3]);
        }

        // ---- epilogue: half2 threshold scan ----
        {
            int cbase = h * 64;
            if (I == J) {
                // mask diagonal elements to -inf (half 0xFC00) in the packed regs
#pragma unroll
                for (int mt = 0; mt < 2; mt++)
#pragma unroll
                    for (int hh = 0; hh < 2; hh++) {
                        int rl = wm * 32 + mt * 16 + hh * 8 + (lane >> 2);
#pragma unroll
                        for (int nt = 0; nt < 4; nt++)
#pragma unroll
                            for (int e = 0; e < 2; e++) {
                                int cl = cbase + wn * 32 + nt * 8 + (lane & 3) * 2 + e;
                                if (rl == cl) {
                                    uint32_t w = acc[mt][nt][hh];
                                    acc[mt][nt][hh] = e ? ((w & 0x0000FFFFu) | 0xFC000000u)
                                                        : ((w & 0xFFFF0000u) | 0x0000FC00u);
                                }
                            }
                    }
            }
            const __half2* tC2 = (const __half2*)(thrC + (it & 1) * 64);
            bool f = false;
#pragma unroll
            for (int mt = 0; mt < 2; mt++) {
                __half2 tr0 = __half2half2(sThrRh[wm * 32 + mt * 16 + (lane >> 2)]);
                __half2 tr1 = __half2half2(sThrRh[wm * 32 + mt * 16 + 8 + (lane >> 2)]);
#pragma unroll
                for (int nt = 0; nt < 4; nt++) {
                    __half2 tc = tC2[wn * 16 + nt * 4 + (lane & 3)];
                    __half2 v0 = *(__half2*)&acc[mt][nt][0];
                    __half2 v1 = *(__half2*)&acc[mt][nt][1];
                    f |= (!__hble2(v0, tr0)) | (!__hble2(v0, tc));
                    f |= (!__hble2(v1, tr1)) | (!__hble2(v1, tc));
                }
            }
            if (__any_sync(0xffffffffu, f) && lane == 0) atomicAdd(&g_flagcnt, 1);
        }

        CP_WAIT0();
        __syncthreads();

        if (it + 1 < cnt && In != I) {
            fillA256(A_s, In * 128, tid);
            if (tid < 128) sThrRh[tid] = g_thrH[In * 128 + tid];
            __syncthreads();
        }
        I = In; J = Jn; h = hn;
    }
}

// ---------------------------------------------------------------- exact fallback
__global__ void __launch_bounds__(512, 2)
k_exact(const int* __restrict__ labels) {
    if (g_flagcnt == 0) return;
    extern __shared__ char dsm[];
    __shared__ float2 s_red[128][4];
    __shared__ float  s_seed[128];

    char* A_s  = dsm;
    char* B_s  = dsm + 32768;
    unsigned char* sLbl = (unsigned char*)(dsm + 98304);
    uint32_t A_u = smem_u32(A_s);
    uint32_t B_u = smem_u32(B_s);

    int tid  = threadIdx.x;
    int lane = tid & 31;
    int wid  = tid >> 5;
    int wm   = wid >> 2;
    int wn   = wid & 3;
    int r    = blockIdx.x >> 2;
    int qd   = blockIdx.x & 3;
    int i0   = r * 128;
    int j0   = qd * NQ;

    fillA512(A_s, i0, tid);
    fillB128_async(B_u, j0, tid);
    CP_COMMIT();
    {
        int4 L = ((const int4*)(labels + j0))[tid];
        ((uint32_t*)sLbl)[tid] = (uint32_t)(L.x & 255) | ((uint32_t)(L.y & 255) << 8)
                               | ((uint32_t)(L.z & 255) << 16) | ((uint32_t)(L.w & 255) << 24);
    }
    {
        int sr = tid >> 2, sq = tid & 3;
        const uint4* rp = (const uint4*)&g_featH[(size_t)(i0 + sr) * KD + sq * 32];
        float sacc = 0.0f;
#pragma unroll
        for (int g = 0; g < 4; g++) {
            uint4 u = rp[g];
            uint32_t w[4] = {u.x, u.y, u.z, u.w};
#pragma unroll
            for (int e = 0; e < 4; e++) {
                float2 fv = __half22float2(*(__half2*)&w[e]);
                sacc = fmaf(fv.x, fv.x, sacc);
                sacc = fmaf(fv.y, fv.y, sacc);
            }
        }
        sacc += __shfl_xor_sync(0xffffffffu, sacc, 1);
        sacc += __shfl_xor_sync(0xffffffffu, sacc, 2);
        if (sq == 0) s_seed[sr] = sacc;
    }

    int myLbl[4];
#pragma unroll
    for (int mt = 0; mt < 2; mt++)
#pragma unroll
        for (int hh = 0; hh < 2; hh++)
            myLbl[mt * 2 + hh] = labels[i0 + wm * 32 + mt * 16 + hh * 8 + (lane >> 2)];

    int q  = lane >> 3;
    int kh = q >> 1;
    uint32_t aAddr[2]; int aRx[2];
#pragma unroll
    for (int mt = 0; mt < 2; mt++) {
        int row = wm * 32 + mt * 16 + (lane & 7) + ((q & 1) << 3);
        aAddr[mt] = A_u + row * 256;
        aRx[mt]   = row & 7;
    }
    uint32_t bOff[2]; int bRx[2];
#pragma unroll
    for (int bt = 0; bt < 2; bt++) {
        int row = wn * 32 + bt * 16 + (lane & 7) + ((q & 1) << 3);
        bOff[bt] = row * 256;
        bRx[bt]  = row & 7;
    }

    CP_WAIT0();
    __syncthreads();

    float mrow[4], prow[4];
#pragma unroll
    for (int mt = 0; mt < 2; mt++)
#pragma unroll
        for (int hh = 0; hh < 2; hh++) {
            mrow[mt * 2 + hh] = s_seed[wm * 32 + mt * 16 + hh * 8 + (lane >> 2)];
            prow[mt * 2 + hh] = 0.0f;
        }

    for (int t = 0; t < NTILES; t++) {
        if (t + 1 < NTILES) {
            fillB128_async(B_u + ((t + 1) & 1) * 32768, j0 + (t + 1) * 128, tid);
            CP_COMMIT();
        }

        uint32_t bu = B_u + (t & 1) * 32768;
        float acc[2][4][4];
#pragma unroll
        for (int a = 0; a < 2; a++)
#pragma unroll
            for (int b = 0; b < 4; b++)
#pragma unroll
                for (int cc = 0; cc < 4; cc++) acc[a][b][cc] = 0.0f;

#pragma unroll
        for (int ks = 0; ks < 8; ks++) {
            uint32_t b0[4], b1[4], a0[4], a1[4];
            LDSM_X4(b0[0], b0[1], b0[2], b0[3], bu + bOff[0] + (((ks * 2 + kh) ^ bRx[0]) << 4));
            LDSM_X4(b1[0], b1[1], b1[2], b1[3], bu + bOff[1] + (((ks * 2 + kh) ^ bRx[1]) << 4));
            LDSM_X4(a0[0], a0[1], a0[2], a0[3], aAddr[0] + (((ks * 2 + kh) ^ aRx[0]) << 4));
            LDSM_X4(a1[0], a1[1], a1[2], a1[3], aAddr[1] + (((ks * 2 + kh) ^ aRx[1]) << 4));
            MMA16816F(acc[0][0], a0[0], a0[1], a0[2], a0[3], b0[0], b0[2]);
            MMA16816F(acc[0][1], a0[0], a0[1], a0[2], a0[3], b0[1], b0[3]);
            MMA16816F(acc[0][2], a0[0], a0[1], a0[2], a0[3], b1[0], b1[2]);
            MMA16816F(acc[0][3], a0[0], a0[1], a0[2], a0[3], b1[1], b1[3]);
            MMA16816F(acc[1][0], a1[0], a1[1], a1[2], a1[3], b0[0], b0[2]);
            MMA16816F(acc[1][1], a1[0], a1[1], a1[2], a1[3], b0[1], b0[3]);
            MMA16816F(acc[1][2], a1[0], a1[1], a1[2], a1[3], b1[0], b1[2]);
            MMA16816F(acc[1][3], a1[0], a1[1], a1[2], a1[3], b1[1], b1[3]);
        }

#pragma unroll
        for (int mt = 0; mt < 2; mt++) {
#pragma unroll
            for (int hh = 0; hh < 2; hh++) {
                int ri = mt * 2 + hh;
                float tmax = acc[mt][0][hh * 2];
                tmax = fmaxf(tmax, acc[mt][0][hh * 2 + 1]);
#pragma unroll
                for (int nt = 1; nt < 4; nt++) {
                    tmax = fmaxf(tmax, acc[mt][nt][hh * 2]);
                    tmax = fmaxf(tmax, acc[mt][nt][hh * 2 + 1]);
                }
                if (__builtin_expect(tmax > mrow[ri] - THRESH, 0)) {
                    float newm = fmaxf(mrow[ri], tmax);
                    prow[ri] *= __expf(mrow[ri] - newm);
                    int ml = myLbl[ri];
#pragma unroll
                    for (int nt = 0; nt < 4; nt++)
#pragma unroll
                        for (int e = 0; e < 2; e++) {
                            float v = acc[mt][nt][hh * 2 + e];
                            if (v > newm - THRESH) {
                                int col = t * 128 + wn * 32 + nt * 8 + (lane & 3) * 2 + e;
                                if ((int)sLbl[col] != ml) prow[ri] += __expf(v - newm);
                            }
                        }
                    mrow[ri] = newm;
                }
            }
        }

        CP_WAIT0();
        __syncthreads();
    }

#pragma unroll
    for (int mt = 0; mt < 2; mt++)
#pragma unroll
        for (int hh = 0; hh < 2; hh++) {
            int ri = mt * 2 + hh;
            float m_ = mrow[ri], p_ = prow[ri];
#pragma unroll
            for (int off = 1; off <= 2; off <<= 1) {
                float om = __shfl_xor_sync(0xffffffffu, m_, off);
                float op = __shfl_xor_sync(0xffffffffu, p_, off);
                float M = fmaxf(m_, om);
                p_ = p_ * expf(m_ - M) + op * expf(om - M);
                m_ = M;
            }
            if ((lane & 3) == 0) {
                int rowloc = wm * 32 + mt * 16 + hh * 8 + (lane >> 2);
                s_red[rowloc][wn] = make_float2(m_, p_);
            }
        }
    __syncthreads();
    if (tid < 128) {
        float2 q0 = s_red[tid][0], q1 = s_red[tid][1];
        float2 q2 = s_red[tid][2], q3 = s_red[tid][3];
        float M = fmaxf(fmaxf(q0.x, q1.x), fmaxf(q2.x, q3.x));
        float P = q0.y * expf(q0.x - M) + q1.y * expf(q1.x - M)
                + q2.y * expf(q2.x - M) + q3.y * expf(q3.x - M);
        g_pm[(size_t)qd * MD + i0 + tid] = make_float2(M, P);
    }
}

// --------------------------- finalize: reduce + last-block writes out
__global__ void k_fsum(const int* __restrict__ labels,
                       const float* __restrict__ ious,
                       float* __restrict__ out) {
    __shared__ float ss[32], sc[32];
    __shared__ float s_pc[NCLS];
    int tid = threadIdx.x, lane = tid & 31, wid = tid >> 5;
    int i = blockIdx.x * 1024 + tid;

    if (tid < NCLS) s_pc[tid] = (float)(g_hist[tid] - 1);
    float iou = ious[i];
    int l = labels[i];
    l = l < 0 ? 0 : (l >= NCLS ? NCLS - 1 : l);
    int flg = g_flagcnt;
    float ns = 0.0f;
    if (flg) {
        float2 a = g_pm[i], b = g_pm[MD + i];
        float2 c = g_pm[2 * MD + i], d = g_pm[3 * MD + i];
        float M = fmaxf(fmaxf(a.x, b.x), fmaxf(c.x, d.x));
        ns = a.y * expf(a.x - M) + b.y * expf(b.x - M)
           + c.y * expf(c.x - M) + d.y * expf(d.x - M);
    }
    __syncthreads();
    float pc = s_pc[l];
    bool keep = (iou >= 0.5f);
    float term = keep ? ns / pc : 0.0f;        // kept 0/0 -> nan, matches ref
    float cnt1 = keep ? 1.0f : 0.0f;
#pragma unroll
    for (int off = 16; off > 0; off >>= 1) {
        term += __shfl_xor_sync(0xffffffffu, term, off);
        cnt1 += __shfl_xor_sync(0xffffffffu, cnt1, off);
    }
    if (lane == 0) { ss[wid] = term; sc[wid] = cnt1; }
    __syncthreads();
    if (wid == 0) {
        float t = ss[lane], c2 = sc[lane];
#pragma unroll
        for (int off = 16; off > 0; off >>= 1) {
            t  += __shfl_xor_sync(0xffffffffu, t, off);
            c2 += __shfl_xor_sync(0xffffffffu, c2, off);
        }
        if (lane == 0) {
            atomicAdd(&g_sum, t);
            atomicAdd(&g_cnt, c2);
            __threadfence();
            int ticket = atomicAdd(&g_done, 1);
            if (ticket == 7) {
                __threadfence();
                float S = *(volatile float*)&g_sum;
                float C = *(volatile float*)&g_cnt;
                out[0] = S / C;
            }
        }
    }
}

// ---------------------------------------------------------------- launch
extern "C" void kernel_launch(void* const* d_in, const int* in_sizes, int n_in,
                              void* d_out, int out_size) {
    const float* feat   = (const float*)d_in[0];
    const int*   labels = (const int*)  d_in[1];
    const float* ious   = (const float*)d_in[2];
    float*       out    = (float*)d_out;
    (void)in_sizes; (void)n_in; (void)out_size;

    const int smem_p1 = 66560;
    const int smem_ex = 98304 + 2048;
    cudaFuncSetAttribute(k_phase1, cudaFuncAttributeMaxDynamicSharedMemorySize, smem_p1);
    cudaFuncSetAttribute(k_exact,  cudaFuncAttributeMaxDynamicSharedMemorySize, smem_ex);

    k_prep<<<MD * KD / (256 * 8), 256>>>(feat, labels);
    k_phase1<<<P1_CTAS, 256, smem_p1>>>();
    k_exact<<<(MD / 128) * 4, 512, smem_ex>>>(labels);
    k_fsum<<<MD / 1024, 1024>>>(labels, ious, out);
}